// round 9
// baseline (speedup 1.0000x reference)
#include <cuda_runtime.h>

#define D 64
#define NMAX 150016
#define EMAX 4800000
#define LMAX 3
#define NBMAX 1024   // max scan blocks (NMAX/256 = 587)

// Scratch (device globals: allocation-free per harness rules)
__device__ float g_ego[NMAX * D];                 // fp32 embeddings (dense input; row owned by its block)
__device__ unsigned int g_egoh[2][NMAX * 32];     // bf16x2 gather tables (ping-pong across layers)
__device__ float g_all[NMAX * (LMAX + 1) * D];    // concat of [ego0, norm1, norm2, norm3]
__device__ int   g_cnt[NMAX];                     // per-row edge counts
__device__ int   g_rowptr[NMAX + 1];              // CSR row pointers
__device__ int   g_rowcur[NMAX];                  // scatter cursors
__device__ int2  g_edge[EMAX];                    // (val bits, col) sorted by row
__device__ int   g_bsum[NBMAX];                   // per-block count sums
__device__ int   g_boff[NBMAX];                   // exclusive block offsets

// ---- packed f32x2 helpers ---------------------------------------------------
__device__ __forceinline__ void ffma2(unsigned long long& d,
                                      unsigned long long a,
                                      unsigned long long b) {
    asm("fma.rn.f32x2 %0, %1, %2, %0;" : "+l"(d) : "l"(a), "l"(b));
}
__device__ __forceinline__ float2 unpack2(unsigned long long v) {
    float2 r;
    asm("mov.b64 {%0, %1}, %2;" : "=f"(r.x), "=f"(r.y) : "l"(v));
    return r;
}
// fp32 -> bf16 round-to-nearest-even, pure bit ops
__device__ __forceinline__ unsigned int f2bf_rn(float f) {
    unsigned int x = __float_as_uint(f);
    return (x + 0x7FFFu + ((x >> 16) & 1u)) >> 16;
}
__device__ __forceinline__ unsigned int packbf2(float lo, float hi) {
    return f2bf_rn(lo) | (f2bf_rn(hi) << 16);
}

// ---------------------------------------------------------------------------
// init: ego = concat(user_emb, item_emb); egoh[0] = bf16(ego); all[:,0:64] = ego
// ---------------------------------------------------------------------------
__global__ void init_kernel(const float* __restrict__ ue,
                            const float* __restrict__ ie,
                            int n_user, int n) {
    int total = n * (D / 4);
    for (int i = blockIdx.x * blockDim.x + threadIdx.x; i < total;
         i += gridDim.x * blockDim.x) {
        int row = i >> 4;
        int q4 = i & 15;
        float4 v;
        if (row < n_user) v = *(const float4*)(ue + row * D + q4 * 4);
        else              v = *(const float4*)(ie + (row - n_user) * D + q4 * 4);
        *(float4*)&g_ego[row * D + q4 * 4] = v;
        *(float4*)&g_all[row * ((LMAX + 1) * D) + q4 * 4] = v;
        g_egoh[0][row * 32 + q4 * 2 + 0] = packbf2(v.x, v.y);
        g_egoh[0][row * 32 + q4 * 2 + 1] = packbf2(v.z, v.w);
        if (i < n) g_cnt[i] = 0;
    }
}

// ---------------------------------------------------------------------------
// CSR step 1: histogram of row indices
// ---------------------------------------------------------------------------
__global__ void hist_kernel(const int* __restrict__ arow, int E) {
    int e = blockIdx.x * blockDim.x + threadIdx.x;
    if (e < E) atomicAdd(&g_cnt[__ldg(arow + e)], 1);
}

// ---------------------------------------------------------------------------
// CSR step 2a: per-block sums of counts
// ---------------------------------------------------------------------------
__global__ void bsum_kernel(int n) {
    __shared__ int s[8];
    int i = blockIdx.x * 256 + threadIdx.x;
    int v = (i < n) ? g_cnt[i] : 0;
#pragma unroll
    for (int off = 16; off > 0; off >>= 1)
        v += __shfl_down_sync(0xffffffffu, v, off);
    if ((threadIdx.x & 31) == 0) s[threadIdx.x >> 5] = v;
    __syncthreads();
    if (threadIdx.x < 8) {
        int x = s[threadIdx.x];
#pragma unroll
        for (int off = 4; off > 0; off >>= 1)
            x += __shfl_down_sync(0xffu, x, off, 8);
        if (threadIdx.x == 0) g_bsum[blockIdx.x] = x;
    }
}

// ---------------------------------------------------------------------------
// CSR step 2b: single-block exclusive scan of block sums
// ---------------------------------------------------------------------------
__global__ void bscan_kernel(int nb) {
    __shared__ int s[NBMAX];
    int t = threadIdx.x;
    int v = (t < nb) ? g_bsum[t] : 0;
    s[t] = v;
    __syncthreads();
    for (int off = 1; off < NBMAX; off <<= 1) {
        int x = (t >= off) ? s[t - off] : 0;
        __syncthreads();
        s[t] += x;
        __syncthreads();
    }
    if (t < nb) g_boff[t] = s[t] - v;
}

// ---------------------------------------------------------------------------
// CSR step 2c: per-block scan + global offset -> rowptr, rowcur
// ---------------------------------------------------------------------------
__global__ void rowptr_kernel(int n, int E) {
    __shared__ int s[256];
    int t = threadIdx.x;
    int i = blockIdx.x * 256 + t;
    int v = (i < n) ? g_cnt[i] : 0;
    s[t] = v;
    __syncthreads();
    for (int off = 1; off < 256; off <<= 1) {
        int x = (t >= off) ? s[t - off] : 0;
        __syncthreads();
        s[t] += x;
        __syncthreads();
    }
    if (i < n) {
        int p = g_boff[blockIdx.x] + s[t] - v;
        g_rowptr[i] = p;
        g_rowcur[i] = p;
    }
    if (i == 0) g_rowptr[n] = E;
}

// ---------------------------------------------------------------------------
// CSR step 3: scatter edges into row-sorted order
// ---------------------------------------------------------------------------
__global__ void scatter_kernel(const float* __restrict__ aval,
                               const int* __restrict__ arow,
                               const int* __restrict__ acol, int E) {
    int e = blockIdx.x * blockDim.x + threadIdx.x;
    if (e >= E) return;
    int r = __ldg(arow + e);
    int p = atomicAdd(&g_rowcur[r], 1);
    g_edge[p] = make_int2(__float_as_int(__ldg(aval + e)), __ldg(acol + e));
}

// ---------------------------------------------------------------------------
// bf16 gather FMA (bit-op dequant, fp32 accumulate)
// ---------------------------------------------------------------------------
__device__ __forceinline__ void bf16_fma4(float4& acc, uint2 u, float v) {
    float lo0 = __uint_as_float(u.x << 16);
    float hi0 = __uint_as_float(u.x & 0xFFFF0000u);
    float lo1 = __uint_as_float(u.y << 16);
    float hi1 = __uint_as_float(u.y & 0xFFFF0000u);
    acc.x += v * lo0; acc.y += v * hi0;
    acc.z += v * lo1; acc.w += v * hi1;
}

// ---------------------------------------------------------------------------
// FUSED layer kernel: 64 rows per block.
// Phase A (spmm): side for 64 rows -> SMEM (no global side round-trip).
// Phase B (dense): ego_new = leaky(side@Wgc + bgc + (ego*side)@Wbi + bbi);
//   writes g_ego (own rows), normalized slice of g_all, bf16 mirror egoh[dst].
// Weights live in SMEM (pre-packed f32x2 pairs) to keep regs < 128 for
// 2 blocks/SM -> cross-block overlap of mem-phase and fma-phase.
// Dynamic SMEM layout (floats):
//   s_wg [32*64 f2] | s_wb [32*64 f2] | s_s [64*68] | s_p [16*68] | s_o [16*68] | s_rn[16]
// ---------------------------------------------------------------------------
#define SM_WG 0
#define SM_WB (SM_WG + 32 * 64 * 2)
#define SM_S  (SM_WB + 32 * 64 * 2)
#define SM_P  (SM_S + 64 * 68)
#define SM_O  (SM_P + 16 * 68)
#define SM_RN (SM_O + 16 * 68)
#define SM_TOT (SM_RN + 16)

__global__ void __launch_bounds__(256, 2)
fused_kernel(const float* __restrict__ Wgc, const float* __restrict__ bgc,
             const float* __restrict__ Wbi, const float* __restrict__ bbi,
             int n, int layer, int src) {
    extern __shared__ float sm[];
    unsigned long long* s_wg = (unsigned long long*)&sm[SM_WG];
    unsigned long long* s_wb = (unsigned long long*)&sm[SM_WB];
    float* s_s  = &sm[SM_S];
    float* s_p  = &sm[SM_P];
    float* s_o  = &sm[SM_O];
    float* s_rn = &sm[SM_RN];

    int t = threadIdx.x;
    int row00 = blockIdx.x * 64;

    // Load + pack weights into SMEM: s_wg[k2*64+j] = (W[2k2][j], W[2k2+1][j])
    for (int idx = t; idx < 2048; idx += 256) {
        int k2 = idx >> 6, jj = idx & 63;
        float2* wgf = (float2*)s_wg;
        float2* wbf = (float2*)s_wb;
        wgf[idx] = make_float2(__ldg(Wgc + (2 * k2) * 64 + jj),
                               __ldg(Wgc + (2 * k2 + 1) * 64 + jj));
        wbf[idx] = make_float2(__ldg(Wbi + (2 * k2) * 64 + jj),
                               __ldg(Wbi + (2 * k2 + 1) * 64 + jj));
    }

    // ---------------- Phase A: SpMM for 64 rows -> s_s -------------------
    const uint2* egoh2 = (const uint2*)g_egoh[src];
    {
        int lane = t & 15;
        int rloc = t >> 4;   // 0..15
        for (int sub = 0; sub < 4; sub++) {
            int row = row00 + sub * 16 + rloc;
            float4 a0 = make_float4(0.f, 0.f, 0.f, 0.f);
            float4 a1 = make_float4(0.f, 0.f, 0.f, 0.f);
            if (row < n) {
                int start = __ldg(&g_rowptr[row]);
                int end   = __ldg(&g_rowptr[row + 1]);
                int jx = start;
                if (jx + 4 <= end) {
                    int2 e0 = __ldg(&g_edge[jx + 0]);
                    int2 e1 = __ldg(&g_edge[jx + 1]);
                    int2 e2 = __ldg(&g_edge[jx + 2]);
                    int2 e3 = __ldg(&g_edge[jx + 3]);
                    for (; jx + 8 <= end; jx += 4) {
                        int2 f0 = __ldg(&g_edge[jx + 4]);
                        int2 f1 = __ldg(&g_edge[jx + 5]);
                        int2 f2 = __ldg(&g_edge[jx + 6]);
                        int2 f3 = __ldg(&g_edge[jx + 7]);
                        uint2 x0 = __ldg(&egoh2[e0.y * 16 + lane]);
                        uint2 x1 = __ldg(&egoh2[e1.y * 16 + lane]);
                        uint2 x2 = __ldg(&egoh2[e2.y * 16 + lane]);
                        uint2 x3 = __ldg(&egoh2[e3.y * 16 + lane]);
                        bf16_fma4(a0, x0, __int_as_float(e0.x));
                        bf16_fma4(a1, x1, __int_as_float(e1.x));
                        bf16_fma4(a0, x2, __int_as_float(e2.x));
                        bf16_fma4(a1, x3, __int_as_float(e3.x));
                        e0 = f0; e1 = f1; e2 = f2; e3 = f3;
                    }
                    uint2 x0 = __ldg(&egoh2[e0.y * 16 + lane]);
                    uint2 x1 = __ldg(&egoh2[e1.y * 16 + lane]);
                    uint2 x2 = __ldg(&egoh2[e2.y * 16 + lane]);
                    uint2 x3 = __ldg(&egoh2[e3.y * 16 + lane]);
                    bf16_fma4(a0, x0, __int_as_float(e0.x));
                    bf16_fma4(a1, x1, __int_as_float(e1.x));
                    bf16_fma4(a0, x2, __int_as_float(e2.x));
                    bf16_fma4(a1, x3, __int_as_float(e3.x));
                    jx += 4;
                }
                for (; jx < end; jx++) {
                    int2 e = __ldg(&g_edge[jx]);
                    uint2 x = __ldg(&egoh2[e.y * 16 + lane]);
                    bf16_fma4(a0, x, __int_as_float(e.x));
                }
            }
            a0.x += a1.x; a0.y += a1.y; a0.z += a1.z; a0.w += a1.w;
            *(float4*)&s_s[(sub * 16 + rloc) * 68 + lane * 4] = a0;
        }
    }
    __syncthreads();

    // ---------------- Phase B: dense + norm + writeback ------------------
    int j = t & 63;
    int rg = t >> 6;
    float bias = __ldg(bgc + j) + __ldg(bbi + j);
    unsigned int* egohd = g_egoh[src ^ 1];

    for (int sub = 0; sub < 4; sub++) {
        int row0 = row00 + sub * 16;
        // stage p = ego * side (side already in s_s)
        {
            int base = t * 4;
            int r = base >> 6;
            int c = base & 63;
            int grow = row0 + r;
            float4 sv = *(const float4*)&s_s[(sub * 16 + r) * 68 + c];
            float4 ev = make_float4(0.f, 0.f, 0.f, 0.f);
            if (grow < n) ev = *(const float4*)&g_ego[grow * D + c];
            *(float4*)&s_p[r * 68 + c] =
                make_float4(sv.x * ev.x, sv.y * ev.y, sv.z * ev.z, sv.w * ev.w);
        }
        __syncthreads();

        unsigned long long acc01[4], acc23[4];
#pragma unroll
        for (int rr = 0; rr < 4; rr++) { acc01[rr] = 0ULL; acc23[rr] = 0ULL; }

#pragma unroll
        for (int k4 = 0; k4 < 16; k4++) {
            unsigned long long wg0 = s_wg[(2 * k4) * 64 + j];
            unsigned long long wg1 = s_wg[(2 * k4 + 1) * 64 + j];
            unsigned long long wb0 = s_wb[(2 * k4) * 64 + j];
            unsigned long long wb1 = s_wb[(2 * k4 + 1) * 64 + j];
#pragma unroll
            for (int rr = 0; rr < 4; rr++) {
                int r = rg * 4 + rr;
                ulonglong2 s2 = *(const ulonglong2*)&s_s[(sub * 16 + r) * 68 + k4 * 4];
                ulonglong2 p2 = *(const ulonglong2*)&s_p[r * 68 + k4 * 4];
                ffma2(acc01[rr], s2.x, wg0);
                ffma2(acc23[rr], s2.y, wg1);
                ffma2(acc01[rr], p2.x, wb0);
                ffma2(acc23[rr], p2.y, wb1);
            }
        }

        float aout[4];
#pragma unroll
        for (int rr = 0; rr < 4; rr++) {
            int r = rg * 4 + rr;
            float2 u = unpack2(acc01[rr]);
            float2 w = unpack2(acc23[rr]);
            float a = bias + ((u.x + u.y) + (w.x + w.y));
            a = (a > 0.f) ? a : 0.2f * a;     // leaky_relu(0.2)
            aout[rr] = a;
            s_o[r * 68 + j] = a;
        }
        __syncthreads();

        // Row L2 norms: 16 threads per row
        {
            int r = t >> 4;
            int i = t & 15;
            float ss = 0.f;
#pragma unroll
            for (int q = 0; q < 4; q++) {
                float x = s_o[r * 68 + i + 16 * q];
                ss += x * x;
            }
#pragma unroll
            for (int off = 8; off > 0; off >>= 1)
                ss += __shfl_down_sync(0xffffffffu, ss, off, 16);
            if (i == 0) s_rn[r] = 1.f / fmaxf(sqrtf(ss), 1e-12f);
        }
        __syncthreads();

#pragma unroll
        for (int rr = 0; rr < 4; rr++) {
            int r = rg * 4 + rr;
            int grow = row0 + r;
            if (grow < n) {
                g_ego[grow * D + j] = aout[rr];
                g_all[grow * ((LMAX + 1) * D) + (layer + 1) * D + j] = aout[rr] * s_rn[r];
            }
        }
        // bf16 mirror of ego_new -> destination gather table
#pragma unroll
        for (int w = 0; w < 2; w++) {
            int u = t + w * 256;
            int r = u >> 5;
            int c = u & 31;
            int grow = row0 + r;
            if (grow < n)
                egohd[grow * 32 + c] = packbf2(s_o[r * 68 + 2 * c], s_o[r * 68 + 2 * c + 1]);
        }
        __syncthreads();
    }
}

// ---------------------------------------------------------------------------
// Gather: out[0:B*256) = all[users], out[B*256:2B*256) = all[N_USER+items]
// ---------------------------------------------------------------------------
__global__ void gather_kernel(const int* __restrict__ users,
                              const int* __restrict__ items,
                              float* __restrict__ out,
                              int B, int n_user) {
    int i = blockIdx.x * blockDim.x + threadIdx.x;
    const int stride = (LMAX + 1) * D / 4;
    int total = 2 * B * stride;
    if (i >= total) return;
    int which = (i >= B * stride) ? 1 : 0;
    int ii = i - which * B * stride;
    int b = ii >> 6;
    int q = ii & 63;
    int row = which ? (n_user + __ldg(items + b)) : __ldg(users + b);
    ((float4*)out)[i] = *(const float4*)&g_all[row * ((LMAX + 1) * D) + q * 4];
}

// ---------------------------------------------------------------------------
extern "C" void kernel_launch(void* const* d_in, const int* in_sizes, int n_in,
                              void* d_out, int out_size) {
    const float* ue   = (const float*)d_in[0];
    const float* ie   = (const float*)d_in[1];
    const float* Wgc  = (const float*)d_in[2];
    const float* bgc  = (const float*)d_in[3];
    const float* Wbi  = (const float*)d_in[4];
    const float* bbi  = (const float*)d_in[5];
    const float* aval = (const float*)d_in[6];
    const int*   arow = (const int*)d_in[7];
    const int*   acol = (const int*)d_in[8];
    const int*   users = (const int*)d_in[9];
    const int*   items = (const int*)d_in[10];

    int n_user = in_sizes[0] / D;
    int n_item = in_sizes[1] / D;
    int n = n_user + n_item;
    int E = in_sizes[6];
    int B = in_sizes[9];
    int L = in_sizes[3] / D;
    if (L > LMAX) L = LMAX;

    const int smem_bytes = SM_TOT * 4;
    cudaFuncSetAttribute(fused_kernel,
                         cudaFuncAttributeMaxDynamicSharedMemorySize, smem_bytes);

    {
        int total = n * (D / 4);
        init_kernel<<<(total + 255) / 256, 256>>>(ue, ie, n_user, n);
    }

    // Build CSR once (reused by all L fused calls)
    int nb = (n + 255) / 256;
    hist_kernel<<<(E + 255) / 256, 256>>>(arow, E);
    bsum_kernel<<<nb, 256>>>(n);
    bscan_kernel<<<1, NBMAX>>>(nb);
    rowptr_kernel<<<nb, 256>>>(n, E);
    scatter_kernel<<<(E + 255) / 256, 256>>>(aval, arow, acol, E);

    for (int k = 0; k < L; k++) {
        fused_kernel<<<(n + 63) / 64, 256, smem_bytes>>>(
            Wgc + k * D * D, bgc + k * D, Wbi + k * D * D, bbi + k * D,
            n, k, k & 1);
    }

    {
        int total = 2 * B * ((LMAX + 1) * D / 4);
        gather_kernel<<<(total + 255) / 256, 256>>>(users, items, (float*)d_out, B, n_user);
    }
}

// round 10
// speedup vs baseline: 1.2217x; 1.2217x over previous
#include <cuda_runtime.h>

#define D 64
#define NMAX 150016
#define EMAX 4800000
#define LMAX 3
#define NBMAX 1024   // max scan blocks (NMAX/256 = 587)

// Scratch (device globals: allocation-free per harness rules)
__device__ float g_ego[NMAX * D];                 // fp32 embeddings (dense input)
__device__ unsigned int g_egoh[NMAX * 32];        // bf16x2 mirror (spmm gather input)
__device__ float g_side[NMAX * D];                // SpMM result
__device__ float g_all[NMAX * (LMAX + 1) * D];    // concat of [ego0, norm1, norm2, norm3]
__device__ int   g_cnt[NMAX];                     // per-row edge counts
__device__ int   g_rowptr[NMAX + 1];              // CSR row pointers
__device__ int   g_rowcur[NMAX];                  // scatter cursors
__device__ int2  g_edge[EMAX];                    // (val bits, col) sorted by row
__device__ int   g_bsum[NBMAX];                   // per-block count sums
__device__ int   g_boff[NBMAX];                   // exclusive block offsets

// ---- packed f32x2 helpers ---------------------------------------------------
__device__ __forceinline__ void ffma2(unsigned long long& d,
                                      unsigned long long a,
                                      unsigned long long b) {
    asm("fma.rn.f32x2 %0, %1, %2, %0;" : "+l"(d) : "l"(a), "l"(b));
}
__device__ __forceinline__ unsigned long long pack2(float lo, float hi) {
    unsigned long long r;
    asm("mov.b64 %0, {%1, %2};" : "=l"(r) : "f"(lo), "f"(hi));
    return r;
}
__device__ __forceinline__ float2 unpack2(unsigned long long v) {
    float2 r;
    asm("mov.b64 {%0, %1}, %2;" : "=f"(r.x), "=f"(r.y) : "l"(v));
    return r;
}
// fp32 -> bf16 round-to-nearest-even, pure bit ops (no bf16 intrinsics)
__device__ __forceinline__ unsigned int f2bf_rn(float f) {
    unsigned int x = __float_as_uint(f);
    return (x + 0x7FFFu + ((x >> 16) & 1u)) >> 16;
}
__device__ __forceinline__ unsigned int packbf2(float lo, float hi) {
    return f2bf_rn(lo) | (f2bf_rn(hi) << 16);
}

// ---------------------------------------------------------------------------
// init: ego = concat(user_emb, item_emb); egoh = bf16(ego); all[:,0:64] = ego
// ---------------------------------------------------------------------------
__global__ void init_kernel(const float* __restrict__ ue,
                            const float* __restrict__ ie,
                            int n_user, int n) {
    int total = n * (D / 4);
    for (int i = blockIdx.x * blockDim.x + threadIdx.x; i < total;
         i += gridDim.x * blockDim.x) {
        int row = i >> 4;
        int q4 = i & 15;
        float4 v;
        if (row < n_user) v = *(const float4*)(ue + row * D + q4 * 4);
        else              v = *(const float4*)(ie + (row - n_user) * D + q4 * 4);
        *(float4*)&g_ego[row * D + q4 * 4] = v;
        *(float4*)&g_all[row * ((LMAX + 1) * D) + q4 * 4] = v;
        g_egoh[row * 32 + q4 * 2 + 0] = packbf2(v.x, v.y);
        g_egoh[row * 32 + q4 * 2 + 1] = packbf2(v.z, v.w);
        if (i < n) g_cnt[i] = 0;
    }
}

// ---------------------------------------------------------------------------
// CSR step 1: histogram of row indices
// ---------------------------------------------------------------------------
__global__ void hist_kernel(const int* __restrict__ arow, int E) {
    int e = blockIdx.x * blockDim.x + threadIdx.x;
    if (e < E) atomicAdd(&g_cnt[__ldg(arow + e)], 1);
}

// ---------------------------------------------------------------------------
// CSR step 2a: per-block sums of counts
// ---------------------------------------------------------------------------
__global__ void bsum_kernel(int n) {
    __shared__ int s[8];
    int i = blockIdx.x * 256 + threadIdx.x;
    int v = (i < n) ? g_cnt[i] : 0;
#pragma unroll
    for (int off = 16; off > 0; off >>= 1)
        v += __shfl_down_sync(0xffffffffu, v, off);
    if ((threadIdx.x & 31) == 0) s[threadIdx.x >> 5] = v;
    __syncthreads();
    if (threadIdx.x < 8) {
        int x = s[threadIdx.x];
#pragma unroll
        for (int off = 4; off > 0; off >>= 1)
            x += __shfl_down_sync(0xffu, x, off, 8);
        if (threadIdx.x == 0) g_bsum[blockIdx.x] = x;
    }
}

// ---------------------------------------------------------------------------
// CSR step 2b: single-block exclusive scan of block sums
// ---------------------------------------------------------------------------
__global__ void bscan_kernel(int nb) {
    __shared__ int s[NBMAX];
    int t = threadIdx.x;
    int v = (t < nb) ? g_bsum[t] : 0;
    s[t] = v;
    __syncthreads();
    for (int off = 1; off < NBMAX; off <<= 1) {
        int x = (t >= off) ? s[t - off] : 0;
        __syncthreads();
        s[t] += x;
        __syncthreads();
    }
    if (t < nb) g_boff[t] = s[t] - v;
}

// ---------------------------------------------------------------------------
// CSR step 2c: per-block scan + global offset -> rowptr, rowcur
// ---------------------------------------------------------------------------
__global__ void rowptr_kernel(int n, int E) {
    __shared__ int s[256];
    int t = threadIdx.x;
    int i = blockIdx.x * 256 + t;
    int v = (i < n) ? g_cnt[i] : 0;
    s[t] = v;
    __syncthreads();
    for (int off = 1; off < 256; off <<= 1) {
        int x = (t >= off) ? s[t - off] : 0;
        __syncthreads();
        s[t] += x;
        __syncthreads();
    }
    if (i < n) {
        int p = g_boff[blockIdx.x] + s[t] - v;
        g_rowptr[i] = p;
        g_rowcur[i] = p;
    }
    if (i == 0) g_rowptr[n] = E;
}

// ---------------------------------------------------------------------------
// CSR step 3: scatter edges into row-sorted order
// ---------------------------------------------------------------------------
__global__ void scatter_kernel(const float* __restrict__ aval,
                               const int* __restrict__ arow,
                               const int* __restrict__ acol, int E) {
    int e = blockIdx.x * blockDim.x + threadIdx.x;
    if (e >= E) return;
    int r = __ldg(arow + e);
    int p = atomicAdd(&g_rowcur[r], 1);
    g_edge[p] = make_int2(__float_as_int(__ldg(aval + e)), __ldg(acol + e));
}

// ---------------------------------------------------------------------------
// SpMM (CSR, bf16 gather, fp32 accumulate): 8 lanes per row.
// Each lane covers 8 cols = one uint4 (8 bf16) -> LDG.128 per edge per lane.
// 4 rows per warp -> 4 independent chains, half the LDG issue count of the
// 16-lane scheme at identical bytes.
// ---------------------------------------------------------------------------
__device__ __forceinline__ void bf16_fma8(float4& p0, float4& p1, uint4 u, float v) {
    p0.x += v * __uint_as_float(u.x << 16);
    p0.y += v * __uint_as_float(u.x & 0xFFFF0000u);
    p0.z += v * __uint_as_float(u.y << 16);
    p0.w += v * __uint_as_float(u.y & 0xFFFF0000u);
    p1.x += v * __uint_as_float(u.z << 16);
    p1.y += v * __uint_as_float(u.z & 0xFFFF0000u);
    p1.z += v * __uint_as_float(u.w << 16);
    p1.w += v * __uint_as_float(u.w & 0xFFFF0000u);
}

__global__ void __launch_bounds__(256)
spmm_csr_kernel(int n) {
    int t = threadIdx.x;
    int lane = t & 7;                    // 8 lanes per row
    int row = blockIdx.x * 32 + (t >> 3);
    if (row >= n) return;

    int start = __ldg(&g_rowptr[row]);
    int end   = __ldg(&g_rowptr[row + 1]);

    const uint4* egoh4 = (const uint4*)g_egoh;   // 8 uint4 per row
    float4 a0 = make_float4(0.f, 0.f, 0.f, 0.f);
    float4 a1 = make_float4(0.f, 0.f, 0.f, 0.f);
    float4 b0 = make_float4(0.f, 0.f, 0.f, 0.f);
    float4 b1 = make_float4(0.f, 0.f, 0.f, 0.f);

    int j = start;
    if (j + 4 <= end) {
        int2 e0 = __ldg(&g_edge[j + 0]);
        int2 e1 = __ldg(&g_edge[j + 1]);
        int2 e2 = __ldg(&g_edge[j + 2]);
        int2 e3 = __ldg(&g_edge[j + 3]);
        for (; j + 8 <= end; j += 4) {
            int2 f0 = __ldg(&g_edge[j + 4]);
            int2 f1 = __ldg(&g_edge[j + 5]);
            int2 f2 = __ldg(&g_edge[j + 6]);
            int2 f3 = __ldg(&g_edge[j + 7]);
            uint4 x0 = __ldg(&egoh4[e0.y * 8 + lane]);
            uint4 x1 = __ldg(&egoh4[e1.y * 8 + lane]);
            uint4 x2 = __ldg(&egoh4[e2.y * 8 + lane]);
            uint4 x3 = __ldg(&egoh4[e3.y * 8 + lane]);
            bf16_fma8(a0, a1, x0, __int_as_float(e0.x));
            bf16_fma8(b0, b1, x1, __int_as_float(e1.x));
            bf16_fma8(a0, a1, x2, __int_as_float(e2.x));
            bf16_fma8(b0, b1, x3, __int_as_float(e3.x));
            e0 = f0; e1 = f1; e2 = f2; e3 = f3;
        }
        {
            uint4 x0 = __ldg(&egoh4[e0.y * 8 + lane]);
            uint4 x1 = __ldg(&egoh4[e1.y * 8 + lane]);
            uint4 x2 = __ldg(&egoh4[e2.y * 8 + lane]);
            uint4 x3 = __ldg(&egoh4[e3.y * 8 + lane]);
            bf16_fma8(a0, a1, x0, __int_as_float(e0.x));
            bf16_fma8(b0, b1, x1, __int_as_float(e1.x));
            bf16_fma8(a0, a1, x2, __int_as_float(e2.x));
            bf16_fma8(b0, b1, x3, __int_as_float(e3.x));
            j += 4;
        }
    }
    for (; j < end; j++) {
        int2 e = __ldg(&g_edge[j]);
        uint4 x = __ldg(&egoh4[e.y * 8 + lane]);
        bf16_fma8(a0, a1, x, __int_as_float(e.x));
    }
    a0.x += b0.x; a0.y += b0.y; a0.z += b0.z; a0.w += b0.w;
    a1.x += b1.x; a1.y += b1.y; a1.z += b1.z; a1.w += b1.w;
    ((float4*)g_side)[row * 16 + lane * 2 + 0] = a0;
    ((float4*)g_side)[row * 16 + lane * 2 + 1] = a1;
}

// ---------------------------------------------------------------------------
// Dense: ego_new = leaky(side@Wgc + bgc + (ego*side)@Wbi + bbi)
//        all[:, (k+1)*64:] = l2norm(ego_new); ego = ego_new (+ bf16 mirror)
// Block: 256 threads = 64 cols x 4 row-groups; 64 rows per block.
// Weights register-resident (f32x2 packed), FFMA2 inner product.
// ---------------------------------------------------------------------------
__global__ void __launch_bounds__(256, 1)
dense_kernel(const float* __restrict__ Wgc, const float* __restrict__ bgc,
             const float* __restrict__ Wbi, const float* __restrict__ bbi,
             int n, int layer) {
    __shared__ float s_s[16][68];
    __shared__ float s_p[16][68];
    __shared__ float s_o[16][68];
    __shared__ float s_rn[16];

    int t = threadIdx.x;
    int j = t & 63;
    int rg = t >> 6;
    int row00 = blockIdx.x * 64;

    unsigned long long wgp[32], wbp[32];
#pragma unroll
    for (int k2 = 0; k2 < 32; k2++) {
        wgp[k2] = pack2(__ldg(Wgc + (2 * k2) * 64 + j), __ldg(Wgc + (2 * k2 + 1) * 64 + j));
        wbp[k2] = pack2(__ldg(Wbi + (2 * k2) * 64 + j), __ldg(Wbi + (2 * k2 + 1) * 64 + j));
    }
    float bias = __ldg(bgc + j) + __ldg(bbi + j);

    for (int sub = 0; sub < 4; sub++) {
        int row0 = row00 + sub * 16;
        {
            int base = t * 4;
            int r = base >> 6;
            int c = base & 63;
            int grow = row0 + r;
            float4 sv = make_float4(0.f, 0.f, 0.f, 0.f);
            float4 ev = sv;
            if (grow < n) {
                sv = *(const float4*)&g_side[grow * D + c];
                ev = *(const float4*)&g_ego[grow * D + c];
            }
            *(float4*)&s_s[r][c] = sv;
            float4 pv = make_float4(sv.x * ev.x, sv.y * ev.y, sv.z * ev.z, sv.w * ev.w);
            *(float4*)&s_p[r][c] = pv;
        }
        __syncthreads();

        unsigned long long acc01[4], acc23[4];
#pragma unroll
        for (int rr = 0; rr < 4; rr++) { acc01[rr] = 0ULL; acc23[rr] = 0ULL; }

#pragma unroll
        for (int k4 = 0; k4 < 16; k4++) {
#pragma unroll
            for (int rr = 0; rr < 4; rr++) {
                int r = rg * 4 + rr;
                ulonglong2 s2 = *(const ulonglong2*)&s_s[r][k4 * 4];
                ulonglong2 p2 = *(const ulonglong2*)&s_p[r][k4 * 4];
                ffma2(acc01[rr], s2.x, wgp[2 * k4 + 0]);
                ffma2(acc23[rr], s2.y, wgp[2 * k4 + 1]);
                ffma2(acc01[rr], p2.x, wbp[2 * k4 + 0]);
                ffma2(acc23[rr], p2.y, wbp[2 * k4 + 1]);
            }
        }

        float aout[4];
#pragma unroll
        for (int rr = 0; rr < 4; rr++) {
            int r = rg * 4 + rr;
            float2 u = unpack2(acc01[rr]);
            float2 w = unpack2(acc23[rr]);
            float a = bias + ((u.x + u.y) + (w.x + w.y));
            a = (a > 0.f) ? a : 0.2f * a;     // leaky_relu(0.2)
            aout[rr] = a;
            s_o[r][j] = a;
        }
        __syncthreads();

        // Row L2 norms: 16 threads per row
        {
            int r = t >> 4;
            int i = t & 15;
            float ss = 0.f;
#pragma unroll
            for (int q = 0; q < 4; q++) {
                float x = s_o[r][i + 16 * q];
                ss += x * x;
            }
#pragma unroll
            for (int off = 8; off > 0; off >>= 1)
                ss += __shfl_down_sync(0xffffffffu, ss, off, 16);
            if (i == 0) s_rn[r] = 1.f / fmaxf(sqrtf(ss), 1e-12f);
        }
        __syncthreads();

#pragma unroll
        for (int rr = 0; rr < 4; rr++) {
            int r = rg * 4 + rr;
            int grow = row0 + r;
            if (grow < n) {
                g_ego[grow * D + j] = aout[rr];
                g_all[grow * ((LMAX + 1) * D) + (layer + 1) * D + j] = aout[rr] * s_rn[r];
            }
        }
        // bf16 mirror of ego_new from the (synced) s_o tile: 2 stores/thread
#pragma unroll
        for (int w = 0; w < 2; w++) {
            int u = t + w * 256;
            int r = u >> 5;
            int c = u & 31;
            int grow = row0 + r;
            if (grow < n)
                g_egoh[grow * 32 + c] = packbf2(s_o[r][2 * c], s_o[r][2 * c + 1]);
        }
        __syncthreads();
    }
}

// ---------------------------------------------------------------------------
// Gather: out[0:B*256) = all[users], out[B*256:2B*256) = all[N_USER+items]
// ---------------------------------------------------------------------------
__global__ void gather_kernel(const int* __restrict__ users,
                              const int* __restrict__ items,
                              float* __restrict__ out,
                              int B, int n_user) {
    int i = blockIdx.x * blockDim.x + threadIdx.x;
    const int stride = (LMAX + 1) * D / 4;
    int total = 2 * B * stride;
    if (i >= total) return;
    int which = (i >= B * stride) ? 1 : 0;
    int ii = i - which * B * stride;
    int b = ii >> 6;
    int q = ii & 63;
    int row = which ? (n_user + __ldg(items + b)) : __ldg(users + b);
    ((float4*)out)[i] = *(const float4*)&g_all[row * ((LMAX + 1) * D) + q * 4];
}

// ---------------------------------------------------------------------------
extern "C" void kernel_launch(void* const* d_in, const int* in_sizes, int n_in,
                              void* d_out, int out_size) {
    const float* ue   = (const float*)d_in[0];
    const float* ie   = (const float*)d_in[1];
    const float* Wgc  = (const float*)d_in[2];
    const float* bgc  = (const float*)d_in[3];
    const float* Wbi  = (const float*)d_in[4];
    const float* bbi  = (const float*)d_in[5];
    const float* aval = (const float*)d_in[6];
    const int*   arow = (const int*)d_in[7];
    const int*   acol = (const int*)d_in[8];
    const int*   users = (const int*)d_in[9];
    const int*   items = (const int*)d_in[10];

    int n_user = in_sizes[0] / D;
    int n_item = in_sizes[1] / D;
    int n = n_user + n_item;
    int E = in_sizes[6];
    int B = in_sizes[9];
    int L = in_sizes[3] / D;
    if (L > LMAX) L = LMAX;

    {
        int total = n * (D / 4);
        init_kernel<<<(total + 255) / 256, 256>>>(ue, ie, n_user, n);
    }

    // Build CSR once (reused by all L spmm calls)
    int nb = (n + 255) / 256;
    hist_kernel<<<(E + 255) / 256, 256>>>(arow, E);
    bsum_kernel<<<nb, 256>>>(n);
    bscan_kernel<<<1, NBMAX>>>(nb);
    rowptr_kernel<<<nb, 256>>>(n, E);
    scatter_kernel<<<(E + 255) / 256, 256>>>(aval, arow, acol, E);

    for (int k = 0; k < L; k++) {
        spmm_csr_kernel<<<(n + 31) / 32, 256>>>(n);
        dense_kernel<<<(n + 63) / 64, 256>>>(Wgc + k * D * D, bgc + k * D,
                                             Wbi + k * D * D, bbi + k * D,
                                             n, k);
    }

    {
        int total = 2 * B * ((LMAX + 1) * D / 4);
        gather_kernel<<<(total + 255) / 256, 256>>>(users, items, (float*)d_out, B, n_user);
    }
}

// round 11
// speedup vs baseline: 1.2865x; 1.0531x over previous
#include <cuda_runtime.h>

#define D 64
#define NMAX 150016
#define EMAX 4800000
#define LMAX 3
#define NBMAX 1024   // max scan blocks (NMAX/256 = 587)

// Scratch (device globals: allocation-free per harness rules)
__device__ unsigned int g_egoh[NMAX * 32];        // bf16x2 embeddings (spmm gather + dense p input)
__device__ float g_side[NMAX * D];                // SpMM result
__device__ float g_all[NMAX * (LMAX + 1) * D];    // concat of [ego0, norm1, norm2, norm3]
__device__ int   g_cnt[NMAX];                     // per-row edge counts (zeroed by rowptr_kernel each pass)
__device__ int   g_rowptr[NMAX + 1];              // CSR row pointers
__device__ int   g_rowcur[NMAX];                  // scatter cursors
__device__ int2  g_edge[EMAX];                    // (val bits, col) sorted by row
__device__ int   g_bsum[NBMAX];                   // per-block count sums
__device__ int   g_boff[NBMAX];                   // exclusive block offsets

// ---- packed f32x2 helpers ---------------------------------------------------
__device__ __forceinline__ void ffma2(unsigned long long& d,
                                      unsigned long long a,
                                      unsigned long long b) {
    asm("fma.rn.f32x2 %0, %1, %2, %0;" : "+l"(d) : "l"(a), "l"(b));
}
__device__ __forceinline__ unsigned long long pack2(float lo, float hi) {
    unsigned long long r;
    asm("mov.b64 %0, {%1, %2};" : "=l"(r) : "f"(lo), "f"(hi));
    return r;
}
__device__ __forceinline__ float2 unpack2(unsigned long long v) {
    float2 r;
    asm("mov.b64 {%0, %1}, %2;" : "=f"(r.x), "=f"(r.y) : "l"(v));
    return r;
}
// fp32 -> bf16 round-to-nearest-even, pure bit ops
__device__ __forceinline__ unsigned int f2bf_rn(float f) {
    unsigned int x = __float_as_uint(f);
    return (x + 0x7FFFu + ((x >> 16) & 1u)) >> 16;
}
__device__ __forceinline__ unsigned int packbf2(float lo, float hi) {
    return f2bf_rn(lo) | (f2bf_rn(hi) << 16);
}
__device__ __forceinline__ float bf_lo(unsigned int u) { return __uint_as_float(u << 16); }
__device__ __forceinline__ float bf_hi(unsigned int u) { return __uint_as_float(u & 0xFFFF0000u); }

// ---------------------------------------------------------------------------
// init+hist fused: (a) all[:,0:64]=concat(ue,ie), egoh=bf16(same);
//                  (b) histogram of row indices (4 edges per thread, int4)
// g_cnt is zero on entry (module init / previous pass's rowptr_kernel).
// ---------------------------------------------------------------------------
__global__ void init_hist_kernel(const float* __restrict__ ue,
                                 const float* __restrict__ ie,
                                 const int* __restrict__ arow,
                                 int n_user, int n, int E) {
    int tid = blockIdx.x * blockDim.x + threadIdx.x;

    // init part: one float4-chunk per thread
    int total = n * (D / 4);
    if (tid < total) {
        int row = tid >> 4;
        int q4 = tid & 15;
        float4 v;
        if (row < n_user) v = *(const float4*)(ue + row * D + q4 * 4);
        else              v = *(const float4*)(ie + (row - n_user) * D + q4 * 4);
        *(float4*)&g_all[row * ((LMAX + 1) * D) + q4 * 4] = v;
        g_egoh[row * 32 + q4 * 2 + 0] = packbf2(v.x, v.y);
        g_egoh[row * 32 + q4 * 2 + 1] = packbf2(v.z, v.w);
    }

    // hist part: 4 edges per thread
    int e = tid * 4;
    if (e + 4 <= E) {
        int4 r4 = *(const int4*)(arow + e);
        atomicAdd(&g_cnt[r4.x], 1);
        atomicAdd(&g_cnt[r4.y], 1);
        atomicAdd(&g_cnt[r4.z], 1);
        atomicAdd(&g_cnt[r4.w], 1);
    } else {
        for (int k = e; k < E; k++) atomicAdd(&g_cnt[__ldg(arow + k)], 1);
    }
}

// ---------------------------------------------------------------------------
// CSR step 2a: per-block sums of counts
// ---------------------------------------------------------------------------
__global__ void bsum_kernel(int n) {
    __shared__ int s[8];
    int i = blockIdx.x * 256 + threadIdx.x;
    int v = (i < n) ? g_cnt[i] : 0;
#pragma unroll
    for (int off = 16; off > 0; off >>= 1)
        v += __shfl_down_sync(0xffffffffu, v, off);
    if ((threadIdx.x & 31) == 0) s[threadIdx.x >> 5] = v;
    __syncthreads();
    if (threadIdx.x < 8) {
        int x = s[threadIdx.x];
#pragma unroll
        for (int off = 4; off > 0; off >>= 1)
            x += __shfl_down_sync(0xffu, x, off, 8);
        if (threadIdx.x == 0) g_bsum[blockIdx.x] = x;
    }
}

// ---------------------------------------------------------------------------
// CSR step 2b: single-block exclusive scan of block sums
// ---------------------------------------------------------------------------
__global__ void bscan_kernel(int nb) {
    __shared__ int s[NBMAX];
    int t = threadIdx.x;
    int v = (t < nb) ? g_bsum[t] : 0;
    s[t] = v;
    __syncthreads();
    for (int off = 1; off < NBMAX; off <<= 1) {
        int x = (t >= off) ? s[t - off] : 0;
        __syncthreads();
        s[t] += x;
        __syncthreads();
    }
    if (t < nb) g_boff[t] = s[t] - v;
}

// ---------------------------------------------------------------------------
// CSR step 2c: per-block scan + offset -> rowptr, rowcur; re-zero cnt
// ---------------------------------------------------------------------------
__global__ void rowptr_kernel(int n, int E) {
    __shared__ int s[256];
    int t = threadIdx.x;
    int i = blockIdx.x * 256 + t;
    int v = (i < n) ? g_cnt[i] : 0;
    s[t] = v;
    __syncthreads();
    for (int off = 1; off < 256; off <<= 1) {
        int x = (t >= off) ? s[t - off] : 0;
        __syncthreads();
        s[t] += x;
        __syncthreads();
    }
    if (i < n) {
        int p = g_boff[blockIdx.x] + s[t] - v;
        g_rowptr[i] = p;
        g_rowcur[i] = p;
        g_cnt[i] = 0;          // ready for the next graph replay
    }
    if (i == 0) g_rowptr[n] = E;
}

// ---------------------------------------------------------------------------
// CSR step 3: scatter edges into row-sorted order (4 edges per thread)
// ---------------------------------------------------------------------------
__global__ void scatter_kernel(const float* __restrict__ aval,
                               const int* __restrict__ arow,
                               const int* __restrict__ acol, int E) {
    int e = (blockIdx.x * blockDim.x + threadIdx.x) * 4;
    if (e + 4 <= E) {
        int4   r4 = *(const int4*)(arow + e);
        int4   c4 = *(const int4*)(acol + e);
        float4 v4 = *(const float4*)(aval + e);
        int p0 = atomicAdd(&g_rowcur[r4.x], 1);
        int p1 = atomicAdd(&g_rowcur[r4.y], 1);
        int p2 = atomicAdd(&g_rowcur[r4.z], 1);
        int p3 = atomicAdd(&g_rowcur[r4.w], 1);
        g_edge[p0] = make_int2(__float_as_int(v4.x), c4.x);
        g_edge[p1] = make_int2(__float_as_int(v4.y), c4.y);
        g_edge[p2] = make_int2(__float_as_int(v4.z), c4.z);
        g_edge[p3] = make_int2(__float_as_int(v4.w), c4.w);
    } else {
        for (int k = e; k < E; k++) {
            int r = __ldg(arow + k);
            int p = atomicAdd(&g_rowcur[r], 1);
            g_edge[p] = make_int2(__float_as_int(__ldg(aval + k)), __ldg(acol + k));
        }
    }
}

// ---------------------------------------------------------------------------
// SpMM (CSR, bf16 gather via bit-op dequant, fp32 accumulate)
// 16 lanes per row; each lane covers 4 cols = one uint2 (4 bf16).
// ---------------------------------------------------------------------------
__device__ __forceinline__ void bf16_fma4(float4& acc, uint2 u, float v) {
    acc.x += v * bf_lo(u.x); acc.y += v * bf_hi(u.x);
    acc.z += v * bf_lo(u.y); acc.w += v * bf_hi(u.y);
}

__global__ void __launch_bounds__(256)
spmm_csr_kernel(int n) {
    int t = threadIdx.x;
    int lane = t & 15;
    int row = blockIdx.x * 16 + (t >> 4);
    if (row >= n) return;

    int start = __ldg(&g_rowptr[row]);
    int end   = __ldg(&g_rowptr[row + 1]);

    const uint2* egoh2 = (const uint2*)g_egoh;   // 16 uint2 per row
    float4 a0 = make_float4(0.f, 0.f, 0.f, 0.f);
    float4 a1 = make_float4(0.f, 0.f, 0.f, 0.f);

    int j = start;
    if (j + 4 <= end) {
        int2 e0 = __ldg(&g_edge[j + 0]);
        int2 e1 = __ldg(&g_edge[j + 1]);
        int2 e2 = __ldg(&g_edge[j + 2]);
        int2 e3 = __ldg(&g_edge[j + 3]);
        for (; j + 8 <= end; j += 4) {
            int2 f0 = __ldg(&g_edge[j + 4]);
            int2 f1 = __ldg(&g_edge[j + 5]);
            int2 f2 = __ldg(&g_edge[j + 6]);
            int2 f3 = __ldg(&g_edge[j + 7]);
            uint2 x0 = __ldg(&egoh2[e0.y * 16 + lane]);
            uint2 x1 = __ldg(&egoh2[e1.y * 16 + lane]);
            uint2 x2 = __ldg(&egoh2[e2.y * 16 + lane]);
            uint2 x3 = __ldg(&egoh2[e3.y * 16 + lane]);
            bf16_fma4(a0, x0, __int_as_float(e0.x));
            bf16_fma4(a1, x1, __int_as_float(e1.x));
            bf16_fma4(a0, x2, __int_as_float(e2.x));
            bf16_fma4(a1, x3, __int_as_float(e3.x));
            e0 = f0; e1 = f1; e2 = f2; e3 = f3;
        }
        {
            uint2 x0 = __ldg(&egoh2[e0.y * 16 + lane]);
            uint2 x1 = __ldg(&egoh2[e1.y * 16 + lane]);
            uint2 x2 = __ldg(&egoh2[e2.y * 16 + lane]);
            uint2 x3 = __ldg(&egoh2[e3.y * 16 + lane]);
            bf16_fma4(a0, x0, __int_as_float(e0.x));
            bf16_fma4(a1, x1, __int_as_float(e1.x));
            bf16_fma4(a0, x2, __int_as_float(e2.x));
            bf16_fma4(a1, x3, __int_as_float(e3.x));
            j += 4;
        }
    }
    for (; j < end; j++) {
        int2 e = __ldg(&g_edge[j]);
        uint2 x = __ldg(&egoh2[e.y * 16 + lane]);
        bf16_fma4(a0, x, __int_as_float(e.x));
    }
    a0.x += a1.x; a0.y += a1.y; a0.z += a1.z; a0.w += a1.w;
    ((float4*)g_side)[row * 16 + lane] = a0;
}

// ---------------------------------------------------------------------------
// Dense: ego_new = leaky(side@Wgc + bgc + (ego*side)@Wbi + bbi)
//        all[:, (k+1)*64:] = l2norm(ego_new); egoh = bf16(ego_new)
// ego read from the bf16 mirror (dequant); no fp32 ego array.
// Block: 256 threads = 64 cols x 4 row-groups; 64 rows per block.
// ---------------------------------------------------------------------------
__global__ void __launch_bounds__(256, 1)
dense_kernel(const float* __restrict__ Wgc, const float* __restrict__ bgc,
             const float* __restrict__ Wbi, const float* __restrict__ bbi,
             int n, int layer) {
    __shared__ float s_s[16][68];
    __shared__ float s_p[16][68];
    __shared__ float s_o[16][68];
    __shared__ float s_rn[16];

    int t = threadIdx.x;
    int j = t & 63;
    int rg = t >> 6;
    int row00 = blockIdx.x * 64;

    unsigned long long wgp[32], wbp[32];
#pragma unroll
    for (int k2 = 0; k2 < 32; k2++) {
        wgp[k2] = pack2(__ldg(Wgc + (2 * k2) * 64 + j), __ldg(Wgc + (2 * k2 + 1) * 64 + j));
        wbp[k2] = pack2(__ldg(Wbi + (2 * k2) * 64 + j), __ldg(Wbi + (2 * k2 + 1) * 64 + j));
    }
    float bias = __ldg(bgc + j) + __ldg(bbi + j);

    for (int sub = 0; sub < 4; sub++) {
        int row0 = row00 + sub * 16;
        {
            int base = t * 4;
            int r = base >> 6;
            int c = base & 63;
            int grow = row0 + r;
            float4 sv = make_float4(0.f, 0.f, 0.f, 0.f);
            float4 ev = sv;
            if (grow < n) {
                sv = *(const float4*)&g_side[grow * D + c];
                uint2 em = ((const uint2*)g_egoh)[grow * 16 + (c >> 2)];
                ev = make_float4(bf_lo(em.x), bf_hi(em.x), bf_lo(em.y), bf_hi(em.y));
            }
            *(float4*)&s_s[r][c] = sv;
            float4 pv = make_float4(sv.x * ev.x, sv.y * ev.y, sv.z * ev.z, sv.w * ev.w);
            *(float4*)&s_p[r][c] = pv;
        }
        __syncthreads();

        unsigned long long acc01[4], acc23[4];
#pragma unroll
        for (int rr = 0; rr < 4; rr++) { acc01[rr] = 0ULL; acc23[rr] = 0ULL; }

#pragma unroll
        for (int k4 = 0; k4 < 16; k4++) {
#pragma unroll
            for (int rr = 0; rr < 4; rr++) {
                int r = rg * 4 + rr;
                ulonglong2 s2 = *(const ulonglong2*)&s_s[r][k4 * 4];
                ulonglong2 p2 = *(const ulonglong2*)&s_p[r][k4 * 4];
                ffma2(acc01[rr], s2.x, wgp[2 * k4 + 0]);
                ffma2(acc23[rr], s2.y, wgp[2 * k4 + 1]);
                ffma2(acc01[rr], p2.x, wbp[2 * k4 + 0]);
                ffma2(acc23[rr], p2.y, wbp[2 * k4 + 1]);
            }
        }

        float aout[4];
#pragma unroll
        for (int rr = 0; rr < 4; rr++) {
            int r = rg * 4 + rr;
            float2 u = unpack2(acc01[rr]);
            float2 w = unpack2(acc23[rr]);
            float a = bias + ((u.x + u.y) + (w.x + w.y));
            a = (a > 0.f) ? a : 0.2f * a;     // leaky_relu(0.2)
            aout[rr] = a;
            s_o[r][j] = a;
        }
        __syncthreads();

        // Row L2 norms: 16 threads per row
        {
            int r = t >> 4;
            int i = t & 15;
            float ss = 0.f;
#pragma unroll
            for (int q = 0; q < 4; q++) {
                float x = s_o[r][i + 16 * q];
                ss += x * x;
            }
#pragma unroll
            for (int off = 8; off > 0; off >>= 1)
                ss += __shfl_down_sync(0xffffffffu, ss, off, 16);
            if (i == 0) s_rn[r] = 1.f / fmaxf(sqrtf(ss), 1e-12f);
        }
        __syncthreads();

#pragma unroll
        for (int rr = 0; rr < 4; rr++) {
            int r = rg * 4 + rr;
            int grow = row0 + r;
            if (grow < n)
                g_all[grow * ((LMAX + 1) * D) + (layer + 1) * D + j] = aout[rr] * s_rn[r];
        }
        // bf16 mirror of ego_new from the (synced) s_o tile: 2 stores/thread
#pragma unroll
        for (int w = 0; w < 2; w++) {
            int u = t + w * 256;
            int r = u >> 5;
            int c = u & 31;
            int grow = row0 + r;
            if (grow < n)
                g_egoh[grow * 32 + c] = packbf2(s_o[r][2 * c], s_o[r][2 * c + 1]);
        }
        __syncthreads();
    }
}

// ---------------------------------------------------------------------------
// Gather: out[0:B*256) = all[users], out[B*256:2B*256) = all[N_USER+items]
// ---------------------------------------------------------------------------
__global__ void gather_kernel(const int* __restrict__ users,
                              const int* __restrict__ items,
                              float* __restrict__ out,
                              int B, int n_user) {
    int i = blockIdx.x * blockDim.x + threadIdx.x;
    const int stride = (LMAX + 1) * D / 4;
    int total = 2 * B * stride;
    if (i >= total) return;
    int which = (i >= B * stride) ? 1 : 0;
    int ii = i - which * B * stride;
    int b = ii >> 6;
    int q = ii & 63;
    int row = which ? (n_user + __ldg(items + b)) : __ldg(users + b);
    ((float4*)out)[i] = *(const float4*)&g_all[row * ((LMAX + 1) * D) + q * 4];
}

// ---------------------------------------------------------------------------
extern "C" void kernel_launch(void* const* d_in, const int* in_sizes, int n_in,
                              void* d_out, int out_size) {
    const float* ue   = (const float*)d_in[0];
    const float* ie   = (const float*)d_in[1];
    const float* Wgc  = (const float*)d_in[2];
    const float* bgc  = (const float*)d_in[3];
    const float* Wbi  = (const float*)d_in[4];
    const float* bbi  = (const float*)d_in[5];
    const float* aval = (const float*)d_in[6];
    const int*   arow = (const int*)d_in[7];
    const int*   acol = (const int*)d_in[8];
    const int*   users = (const int*)d_in[9];
    const int*   items = (const int*)d_in[10];

    int n_user = in_sizes[0] / D;
    int n_item = in_sizes[1] / D;
    int n = n_user + n_item;
    int E = in_sizes[6];
    int B = in_sizes[9];
    int L = in_sizes[3] / D;
    if (L > LMAX) L = LMAX;

    // Fused init + histogram (cnt is zero on entry; rowptr re-zeroes it)
    {
        int init_items = n * (D / 4);
        int hist_threads = (E + 3) / 4;
        int threads = init_items > hist_threads ? init_items : hist_threads;
        init_hist_kernel<<<(threads + 255) / 256, 256>>>(ue, ie, arow, n_user, n, E);
    }

    // Build CSR once (reused by all L spmm calls)
    int nb = (n + 255) / 256;
    bsum_kernel<<<nb, 256>>>(n);
    bscan_kernel<<<1, NBMAX>>>(nb);
    rowptr_kernel<<<nb, 256>>>(n, E);
    scatter_kernel<<<(E / 4 + 255) / 256 + 1, 256>>>(aval, arow, acol, E);

    for (int k = 0; k < L; k++) {
        spmm_csr_kernel<<<(n + 15) / 16, 256>>>(n);
        dense_kernel<<<(n + 63) / 64, 256>>>(Wgc + k * D * D, bgc + k * D,
                                             Wbi + k * D * D, bbi + k * D,
                                             n, k);
    }

    {
        int total = 2 * B * ((LMAX + 1) * D / 4);
        gather_kernel<<<(total + 255) / 256, 256>>>(users, items, (float*)d_out, B, n_user);
    }
}